// round 1
// baseline (speedup 1.0000x reference)
#include <cuda_runtime.h>
#include <cuda_bf16.h>
#include <math.h>

// Problem constants
#define Bv   2
#define Dv   16
#define Hv   56
#define Wv   56
#define Cv   256
#define NHv  8
#define HDv  32
#define WSv  4
#define SSv  2
#define Nv   64            // tokens per window (4^3)
#define NWIN 784           // windows per batch: 4*14*14
#define BWIN 1568          // total windows
#define Tv   100352        // total tokens  B*D*H*W

// Scratch (device globals; no allocation allowed)
__device__ float g_buf0[(size_t)Tv * 256];    // ln1 out (windowed) / ln2 out (natural)
__device__ float g_buf1[(size_t)Tv * 1024];   // qkv / proj out / fc1 out
__device__ float g_buf2[(size_t)Tv * 256];    // attn out (windowed) / x1 (natural)

// ---------------------------------------------------------------------------
// Block-wide LN helper: 256 threads, one per channel.
__device__ __forceinline__ float block_ln(float v, const float* __restrict__ g,
                                          const float* __restrict__ b, int c) {
    __shared__ float red[2][8];
    float s1 = v, s2 = v * v;
    #pragma unroll
    for (int o = 16; o > 0; o >>= 1) {
        s1 += __shfl_xor_sync(0xffffffffu, s1, o);
        s2 += __shfl_xor_sync(0xffffffffu, s2, o);
    }
    int lane = threadIdx.x & 31, wid = threadIdx.x >> 5;
    if (lane == 0) { red[0][wid] = s1; red[1][wid] = s2; }
    __syncthreads();
    if (wid == 0) {
        float a = red[0][lane & 7], bb = red[1][lane & 7];
        #pragma unroll
        for (int o = 4; o > 0; o >>= 1) {
            a += __shfl_xor_sync(0xffffffffu, a, o);
            bb += __shfl_xor_sync(0xffffffffu, bb, o);
        }
        if (lane == 0) { red[0][0] = a; red[1][0] = bb; }
    }
    __syncthreads();
    float mu = red[0][0] * (1.0f / 256.0f);
    float var = red[1][0] * (1.0f / 256.0f) - mu * mu;
    return (v - mu) * rsqrtf(var + 1e-5f) * g[c] + b[c];
}

// ---------------------------------------------------------------------------
// K1: LN1 + roll(-2) + window partition  ->  g_buf0 [BWIN*64, 256]
__global__ void __launch_bounds__(256) k_ln1_roll_part(
    const float* __restrict__ x, const float* __restrict__ g,
    const float* __restrict__ bta, float* __restrict__ out) {
    int wt = blockIdx.x;            // windowed token index
    int c  = threadIdx.x;
    int i  = wt & 63, b_ = wt >> 6;
    int b = b_ / NWIN, widx = b_ % NWIN;
    int wd = widx / 196, r = widx % 196, wh = r / 14, ww = r % 14;
    int zi = i >> 4, yi = (i >> 2) & 3, xi = i & 3;
    int ds = wd * 4 + zi, hs = wh * 4 + yi, ws = ww * 4 + xi;
    int d = (ds + SSv) & 15;
    int h = hs + SSv; if (h >= Hv) h -= Hv;
    int w = ws + SSv; if (w >= Wv) w -= Wv;
    const float* row = x + ((size_t)((b * Dv + d) * Hv + h) * Wv + w) * Cv;
    float v = row[c];
    out[(size_t)wt * Cv + c] = block_ln(v, g, bta, c);
}

// ---------------------------------------------------------------------------
// K5+K6: x1 = x + reverse(roll(proj_out)),  then LN2
__global__ void __launch_bounds__(256) k_x1_ln2(
    const float* __restrict__ x, const float* __restrict__ projout,
    const float* __restrict__ g, const float* __restrict__ bta,
    float* __restrict__ x1, float* __restrict__ lnout) {
    int t = blockIdx.x;             // natural token index
    int c = threadIdx.x;
    int w = t % Wv, tmp = t / Wv;
    int h = tmp % Hv; tmp /= Hv;
    int d = tmp % Dv; int b = tmp / Dv;
    int ds = (d - SSv) & 15;
    int hs = h - SSv; if (hs < 0) hs += Hv;
    int ws = w - SSv; if (ws < 0) ws += Wv;
    int wt = ((b * NWIN + (ds >> 2) * 196 + (hs >> 2) * 14 + (ws >> 2)) << 6)
             + ((ds & 3) << 4) + ((hs & 3) << 2) + (ws & 3);
    float v = x[(size_t)t * Cv + c] + projout[(size_t)wt * Cv + c];
    x1[(size_t)t * Cv + c] = v;
    lnout[(size_t)t * Cv + c] = block_ln(v, g, bta, c);
}

// ---------------------------------------------------------------------------
// K3: fused windowed attention. One block per (window, head). 128 threads.
__global__ void __launch_bounds__(128) k_attn(
    const float* __restrict__ qkv, const float* __restrict__ rpb,
    float* __restrict__ out) {
    int blk  = blockIdx.x;
    int head = blk & 7;
    int b_   = blk >> 3;
    __shared__ float q[64][33], k[64][33], v[64][33];
    __shared__ float S[64][65];
    __shared__ int   label[64];
    int tid = threadIdx.x;

    const float* base = qkv + (size_t)b_ * 64 * 768 + head * HDv;
    for (int idx = tid; idx < 2048; idx += 128) {
        int i = idx >> 5, dch = idx & 31;
        const float* p = base + (size_t)i * 768 + dch;
        q[i][dch] = p[0] * 0.17677669529663689f;   // hd^-0.5
        k[i][dch] = p[256];
        v[i][dch] = p[512];
    }
    if (tid < 64) {
        int widx = b_ % NWIN;
        int wd = widx / 196, rr = widx % 196, wh = rr / 14, ww = rr % 14;
        int zi = tid >> 4, yi = (tid >> 2) & 3, xi = tid & 3;
        int dg = wd * 4 + zi, hg = wh * 4 + yi, wg = ww * 4 + xi;
        int rd = dg < Dv - WSv ? 0 : (dg < Dv - SSv ? 1 : 2);
        int rh = hg < Hv - WSv ? 0 : (hg < Hv - SSv ? 1 : 2);
        int rw = wg < Wv - WSv ? 0 : (wg < Wv - SSv ? 1 : 2);
        label[tid] = rd * 9 + rh * 3 + rw;
    }
    __syncthreads();

    for (int e = tid; e < 4096; e += 128) {
        int i = e >> 6, j = e & 63;
        float s = 0.f;
        #pragma unroll
        for (int d0 = 0; d0 < 32; d0++) s += q[i][d0] * k[j][d0];
        int zi = i >> 4, yi = (i >> 2) & 3, xi = i & 3;
        int zj = j >> 4, yj = (j >> 2) & 3, xj = j & 3;
        int bi = ((zi - zj + 3) * 49 + (yi - yj + 3) * 7 + (xi - xj + 3)) * NHv + head;
        s += __ldg(&rpb[bi]);
        if (label[i] != label[j]) s -= 100.0f;
        S[i][j] = s;
    }
    __syncthreads();

    if (tid < 64) {
        float m = -1e30f;
        #pragma unroll 8
        for (int j = 0; j < 64; j++) m = fmaxf(m, S[tid][j]);
        float sum = 0.f;
        #pragma unroll 8
        for (int j = 0; j < 64; j++) { float e2 = __expf(S[tid][j] - m); S[tid][j] = e2; sum += e2; }
        float inv = 1.0f / sum;
        #pragma unroll 8
        for (int j = 0; j < 64; j++) S[tid][j] *= inv;
    }
    __syncthreads();

    for (int e = tid; e < 2048; e += 128) {
        int i = e >> 5, dch = e & 31;
        float o = 0.f;
        #pragma unroll
        for (int j = 0; j < 64; j++) o += S[i][j] * v[j][dch];
        out[((size_t)b_ * 64 + i) * Cv + head * HDv + dch] = o;
    }
}

// ---------------------------------------------------------------------------
// Generic tiled fp32 GEMM: C[M,N] = A[M,K] @ B[K,N] + bias,  epilogue variants.
// BM=BN=64, BK=16, 256 threads, 4x4 per thread. M,N div by 64; K div by 16.
// EPI: 0 = none, 1 = exact GELU, 2 = add residual
template<int EPI>
__global__ void __launch_bounds__(256) k_gemm64(
    const float* __restrict__ A, const float* __restrict__ Bw,
    const float* __restrict__ bias, float* __restrict__ C,
    int M, int N, int K, const float* __restrict__ res) {
    __shared__ float As[16][64];
    __shared__ float Bs[16][68];
    int tid = threadIdx.x;
    int tx = tid & 15, ty = tid >> 4;
    int rowBase = blockIdx.y * 64;
    int colBase = blockIdx.x * 64;

    float acc[4][4] = {};

    int ar = tid >> 2;            // 0..63
    int ak = (tid & 3) * 4;       // 0,4,8,12
    int br = tid >> 4;            // 0..15
    int bn = (tid & 15) * 4;      // 0..60
    const float* Aptr = A + (size_t)(rowBase + ar) * K + ak;
    const float* Bptr = Bw + (size_t)br * N + colBase + bn;

    for (int k0 = 0; k0 < K; k0 += 16) {
        float4 a4 = *(const float4*)(Aptr + k0);
        As[ak + 0][ar] = a4.x; As[ak + 1][ar] = a4.y;
        As[ak + 2][ar] = a4.z; As[ak + 3][ar] = a4.w;
        *(float4*)&Bs[br][bn] = *(const float4*)(Bptr + (size_t)k0 * N);
        __syncthreads();
        #pragma unroll
        for (int kk = 0; kk < 16; kk++) {
            float4 a = *(const float4*)&As[kk][ty * 4];
            float4 b = *(const float4*)&Bs[kk][tx * 4];
            acc[0][0] += a.x * b.x; acc[0][1] += a.x * b.y; acc[0][2] += a.x * b.z; acc[0][3] += a.x * b.w;
            acc[1][0] += a.y * b.x; acc[1][1] += a.y * b.y; acc[1][2] += a.y * b.z; acc[1][3] += a.y * b.w;
            acc[2][0] += a.z * b.x; acc[2][1] += a.z * b.y; acc[2][2] += a.z * b.z; acc[2][3] += a.z * b.w;
            acc[3][0] += a.w * b.x; acc[3][1] += a.w * b.y; acc[3][2] += a.w * b.z; acc[3][3] += a.w * b.w;
        }
        __syncthreads();
    }

    int col = colBase + tx * 4;
    float4 bb = *(const float4*)&bias[col];
    #pragma unroll
    for (int i = 0; i < 4; i++) {
        size_t row = (size_t)(rowBase + ty * 4 + i);
        float4 o;
        o.x = acc[i][0] + bb.x; o.y = acc[i][1] + bb.y;
        o.z = acc[i][2] + bb.z; o.w = acc[i][3] + bb.w;
        if (EPI == 1) {
            o.x = 0.5f * o.x * (1.0f + erff(o.x * 0.70710678118654752f));
            o.y = 0.5f * o.y * (1.0f + erff(o.y * 0.70710678118654752f));
            o.z = 0.5f * o.z * (1.0f + erff(o.z * 0.70710678118654752f));
            o.w = 0.5f * o.w * (1.0f + erff(o.w * 0.70710678118654752f));
        }
        if (EPI == 2) {
            float4 r4 = *(const float4*)&res[row * N + col];
            o.x += r4.x; o.y += r4.y; o.z += r4.z; o.w += r4.w;
        }
        *(float4*)&C[row * N + col] = o;
    }
}

// ---------------------------------------------------------------------------
extern "C" void kernel_launch(void* const* d_in, const int* in_sizes, int n_in,
                              void* d_out, int out_size) {
    const float* x      = (const float*)d_in[0];
    const float* n1g    = (const float*)d_in[1];
    const float* n1b    = (const float*)d_in[2];
    const float* qkv_w  = (const float*)d_in[3];
    const float* qkv_b  = (const float*)d_in[4];
    const float* proj_w = (const float*)d_in[5];
    const float* proj_b = (const float*)d_in[6];
    const float* rpb    = (const float*)d_in[7];
    const float* n2g    = (const float*)d_in[8];
    const float* n2b    = (const float*)d_in[9];
    const float* fc1_w  = (const float*)d_in[10];
    const float* fc1_b  = (const float*)d_in[11];
    const float* fc2_w  = (const float*)d_in[12];
    const float* fc2_b  = (const float*)d_in[13];
    float* out = (float*)d_out;

    float *b0, *b1, *b2;
    cudaGetSymbolAddress((void**)&b0, g_buf0);
    cudaGetSymbolAddress((void**)&b1, g_buf1);
    cudaGetSymbolAddress((void**)&b2, g_buf2);

    // 1) LN1 + roll + window partition -> b0 [T,256] (windowed)
    k_ln1_roll_part<<<Tv, 256>>>(x, n1g, n1b, b0);
    // 2) qkv GEMM -> b1 [T,768]
    k_gemm64<0><<<dim3(768 / 64, Tv / 64), 256>>>(b0, qkv_w, qkv_b, b1, Tv, 768, 256, nullptr);
    // 3) fused windowed attention -> b2 [T,256] (windowed)
    k_attn<<<BWIN * NHv, 128>>>(b1, rpb, b2);
    // 4) proj GEMM -> b1 [T,256] (windowed)
    k_gemm64<0><<<dim3(256 / 64, Tv / 64), 256>>>(b2, proj_w, proj_b, b1, Tv, 256, 256, nullptr);
    // 5) x1 = x + reverse(roll back), LN2 -> x1 in b2 (natural), ln in b0
    k_x1_ln2<<<Tv, 256>>>(x, b1, n2g, n2b, b2, b0);
    // 6) fc1 + GELU -> b1 [T,1024]
    k_gemm64<1><<<dim3(1024 / 64, Tv / 64), 256>>>(b0, fc1_w, fc1_b, b1, Tv, 1024, 256, nullptr);
    // 7) fc2 + residual(x1) -> out
    k_gemm64<2><<<dim3(256 / 64, Tv / 64), 256>>>(b1, fc2_w, fc2_b, out, Tv, 256, 1024, b2);
}

// round 2
// speedup vs baseline: 3.3043x; 3.3043x over previous
#include <cuda_runtime.h>
#include <cuda_bf16.h>
#include <math.h>
#include <stdint.h>

// Problem constants
#define Bv   2
#define Dv   16
#define Hv   56
#define Wv   56
#define Cv   256
#define NHv  8
#define HDv  32
#define WSv  4
#define SSv  2
#define NWIN 784           // windows per batch: 4*14*14
#define BWIN 1568          // total windows
#define Tv   100352        // total tokens  B*D*H*W

// ---------------------------------------------------------------------------
// Scratch (device globals; no allocation allowed)
__device__ __nv_bfloat16 g_ln[(size_t)Tv * 256];     // ln1 out (windowed) / ln2 out (natural)
__device__ __nv_bfloat16 g_big[(size_t)Tv * 1024];   // qkv out (768) / fc1 out (1024)
__device__ __nv_bfloat16 g_attn[(size_t)Tv * 256];   // attn out (windowed)
__device__ float         g_proj[(size_t)Tv * 256];   // proj out (windowed, fp32)
__device__ float         g_x1[(size_t)Tv * 256];     // x1 (natural, fp32)
__device__ __nv_bfloat16 g_w[786432];                // bf16 weights: qkv|proj|fc1|fc2

#define WOFF_QKV  0
#define WOFF_PROJ 196608
#define WOFF_FC1  262144
#define WOFF_FC2  524288

// ---------------------------------------------------------------------------
__global__ void k_f2bf(const float* __restrict__ src, __nv_bfloat16* __restrict__ dst, int n) {
    int i = blockIdx.x * 256 + threadIdx.x;
    if (i < n) dst[i] = __float2bfloat16(src[i]);
}

// ---------------------------------------------------------------------------
// Block-wide LN helper: 256 threads, one per channel.
__device__ __forceinline__ float block_ln(float v, const float* __restrict__ g,
                                          const float* __restrict__ b, int c) {
    __shared__ float red[2][8];
    float s1 = v, s2 = v * v;
    #pragma unroll
    for (int o = 16; o > 0; o >>= 1) {
        s1 += __shfl_xor_sync(0xffffffffu, s1, o);
        s2 += __shfl_xor_sync(0xffffffffu, s2, o);
    }
    int lane = threadIdx.x & 31, wid = threadIdx.x >> 5;
    if (lane == 0) { red[0][wid] = s1; red[1][wid] = s2; }
    __syncthreads();
    if (wid == 0) {
        float a = red[0][lane & 7], bb = red[1][lane & 7];
        #pragma unroll
        for (int o = 4; o > 0; o >>= 1) {
            a += __shfl_xor_sync(0xffffffffu, a, o);
            bb += __shfl_xor_sync(0xffffffffu, bb, o);
        }
        if (lane == 0) { red[0][0] = a; red[1][0] = bb; }
    }
    __syncthreads();
    float mu = red[0][0] * (1.0f / 256.0f);
    float var = red[1][0] * (1.0f / 256.0f) - mu * mu;
    return (v - mu) * rsqrtf(var + 1e-5f) * g[c] + b[c];
}

// ---------------------------------------------------------------------------
// K1: LN1 + roll(-2) + window partition  ->  g_ln [BWIN*64, 256]  (bf16)
__global__ void __launch_bounds__(256) k_ln1_roll_part(
    const float* __restrict__ x, const float* __restrict__ g,
    const float* __restrict__ bta, __nv_bfloat16* __restrict__ out) {
    int wt = blockIdx.x;            // windowed token index
    int c  = threadIdx.x;
    int i  = wt & 63, b_ = wt >> 6;
    int b = b_ / NWIN, widx = b_ % NWIN;
    int wd = widx / 196, r = widx % 196, wh = r / 14, ww = r % 14;
    int zi = i >> 4, yi = (i >> 2) & 3, xi = i & 3;
    int ds = wd * 4 + zi, hs = wh * 4 + yi, ws = ww * 4 + xi;
    int d = (ds + SSv) & 15;
    int h = hs + SSv; if (h >= Hv) h -= Hv;
    int w = ws + SSv; if (w >= Wv) w -= Wv;
    const float* row = x + ((size_t)((b * Dv + d) * Hv + h) * Wv + w) * Cv;
    float v = row[c];
    out[(size_t)wt * Cv + c] = __float2bfloat16(block_ln(v, g, bta, c));
}

// ---------------------------------------------------------------------------
// K5: x1 = x + reverse(roll(proj_out)),  then LN2 (bf16)
__global__ void __launch_bounds__(256) k_x1_ln2(
    const float* __restrict__ x, const float* __restrict__ projout,
    const float* __restrict__ g, const float* __restrict__ bta,
    float* __restrict__ x1, __nv_bfloat16* __restrict__ lnout) {
    int t = blockIdx.x;             // natural token index
    int c = threadIdx.x;
    int w = t % Wv, tmp = t / Wv;
    int h = tmp % Hv; tmp /= Hv;
    int d = tmp % Dv; int b = tmp / Dv;
    int ds = (d - SSv) & 15;
    int hs = h - SSv; if (hs < 0) hs += Hv;
    int ws = w - SSv; if (ws < 0) ws += Wv;
    int wt = ((b * NWIN + (ds >> 2) * 196 + (hs >> 2) * 14 + (ws >> 2)) << 6)
             + ((ds & 3) << 4) + ((hs & 3) << 2) + (ws & 3);
    float v = x[(size_t)t * Cv + c] + projout[(size_t)wt * Cv + c];
    x1[(size_t)t * Cv + c] = v;
    lnout[(size_t)t * Cv + c] = __float2bfloat16(block_ln(v, g, bta, c));
}

// ---------------------------------------------------------------------------
// K3: fused windowed attention (bf16 in / bf16 out, fp32 compute).
__global__ void __launch_bounds__(128) k_attn(
    const __nv_bfloat16* __restrict__ qkv, const float* __restrict__ rpb,
    __nv_bfloat16* __restrict__ out) {
    int blk  = blockIdx.x;
    int head = blk & 7;
    int b_   = blk >> 3;
    __shared__ float q[64][33], k[64][33], v[64][33];
    __shared__ float S[64][65];
    __shared__ int   label[64];
    int tid = threadIdx.x;

    const __nv_bfloat16* base = qkv + (size_t)b_ * 64 * 768 + head * HDv;
    for (int idx = tid; idx < 2048; idx += 128) {
        int i = idx >> 5, dch = idx & 31;
        const __nv_bfloat16* p = base + (size_t)i * 768 + dch;
        q[i][dch] = __bfloat162float(p[0]) * 0.17677669529663689f;   // hd^-0.5
        k[i][dch] = __bfloat162float(p[256]);
        v[i][dch] = __bfloat162float(p[512]);
    }
    if (tid < 64) {
        int widx = b_ % NWIN;
        int wd = widx / 196, rr = widx % 196, wh = rr / 14, ww = rr % 14;
        int zi = tid >> 4, yi = (tid >> 2) & 3, xi = tid & 3;
        int dg = wd * 4 + zi, hg = wh * 4 + yi, wg = ww * 4 + xi;
        int rd = dg < Dv - WSv ? 0 : (dg < Dv - SSv ? 1 : 2);
        int rh = hg < Hv - WSv ? 0 : (hg < Hv - SSv ? 1 : 2);
        int rw = wg < Wv - WSv ? 0 : (wg < Wv - SSv ? 1 : 2);
        label[tid] = rd * 9 + rh * 3 + rw;
    }
    __syncthreads();

    for (int e = tid; e < 4096; e += 128) {
        int i = e >> 6, j = e & 63;
        float s = 0.f;
        #pragma unroll
        for (int d0 = 0; d0 < 32; d0++) s += q[i][d0] * k[j][d0];
        int zi = i >> 4, yi = (i >> 2) & 3, xi = i & 3;
        int zj = j >> 4, yj = (j >> 2) & 3, xj = j & 3;
        int bi = ((zi - zj + 3) * 49 + (yi - yj + 3) * 7 + (xi - xj + 3)) * NHv + head;
        s += __ldg(&rpb[bi]);
        if (label[i] != label[j]) s -= 100.0f;
        S[i][j] = s;
    }
    __syncthreads();

    if (tid < 64) {
        float m = -1e30f;
        #pragma unroll 8
        for (int j = 0; j < 64; j++) m = fmaxf(m, S[tid][j]);
        float sum = 0.f;
        #pragma unroll 8
        for (int j = 0; j < 64; j++) { float e2 = __expf(S[tid][j] - m); S[tid][j] = e2; sum += e2; }
        float inv = 1.0f / sum;
        #pragma unroll 8
        for (int j = 0; j < 64; j++) S[tid][j] *= inv;
    }
    __syncthreads();

    for (int e = tid; e < 2048; e += 128) {
        int i = e >> 5, dch = e & 31;
        float o = 0.f;
        #pragma unroll
        for (int j = 0; j < 64; j++) o += S[i][j] * v[j][dch];
        out[((size_t)b_ * 64 + i) * Cv + head * HDv + dch] = __float2bfloat16(o);
    }
}

// ---------------------------------------------------------------------------
// bf16 tensor-core GEMM: C[M,N] = A[M,K] @ B[K,N] + bias (+epilogue)
// BM=128, BN=128, BK=32, 256 threads (8 warps, 4x2), warp tile 32x64.
// A row-major bf16, B row-major bf16. M%128==0, N%128==0, K%32==0.
// EPI: 0 = bf16 out, 1 = fp32 out, 2 = GELU + bf16 out, 3 = +res, fp32 out
#define SA_STRIDE 40     // bf16 elems per A smem row (32 used) -> 80B, conflict-free ldmatrix
#define SB_STRIDE 136    // bf16 elems per B smem row (128 used) -> 272B, conflict-free ldmatrix

__device__ __forceinline__ void ldsm_x4(uint32_t& r0, uint32_t& r1, uint32_t& r2, uint32_t& r3,
                                        uint32_t addr) {
    asm volatile("ldmatrix.sync.aligned.m8n8.x4.shared.b16 {%0,%1,%2,%3}, [%4];\n"
                 : "=r"(r0), "=r"(r1), "=r"(r2), "=r"(r3) : "r"(addr));
}
__device__ __forceinline__ void ldsm_x4t(uint32_t& r0, uint32_t& r1, uint32_t& r2, uint32_t& r3,
                                         uint32_t addr) {
    asm volatile("ldmatrix.sync.aligned.m8n8.x4.trans.shared.b16 {%0,%1,%2,%3}, [%4];\n"
                 : "=r"(r0), "=r"(r1), "=r"(r2), "=r"(r3) : "r"(addr));
}
__device__ __forceinline__ void mma_bf16(float& d0, float& d1, float& d2, float& d3,
                                         uint32_t a0, uint32_t a1, uint32_t a2, uint32_t a3,
                                         uint32_t b0, uint32_t b1) {
    asm volatile("mma.sync.aligned.m16n8k16.row.col.f32.bf16.bf16.f32 "
                 "{%0,%1,%2,%3}, {%4,%5,%6,%7}, {%8,%9}, {%0,%1,%2,%3};\n"
                 : "+f"(d0), "+f"(d1), "+f"(d2), "+f"(d3)
                 : "r"(a0), "r"(a1), "r"(a2), "r"(a3), "r"(b0), "r"(b1));
}
__device__ __forceinline__ void cp16(uint32_t dst, const void* src) {
    asm volatile("cp.async.cg.shared.global [%0], [%1], 16;\n" :: "r"(dst), "l"(src));
}

template<int EPI>
__global__ void __launch_bounds__(256) k_mmagemm(
    const __nv_bfloat16* __restrict__ A, const __nv_bfloat16* __restrict__ Bw,
    const float* __restrict__ bias, void* __restrict__ Cout,
    int M, int N, int K, const float* __restrict__ res) {
    __shared__ __nv_bfloat16 sA[2][128 * SA_STRIDE];
    __shared__ __nv_bfloat16 sB[2][32 * SB_STRIDE];

    int tid  = threadIdx.x;
    int lane = tid & 31, warp = tid >> 5;
    int wy = warp >> 1, wx = warp & 1;       // 4 x 2 warps
    int rowBase = blockIdx.y * 128;
    int colBase = blockIdx.x * 128;

    // ---- load thread mapping (16B chunks) ----
    int a_r0 = tid >> 2;                 // 0..63  (and +64)
    int a_kc = (tid & 3) * 8;            // 0,8,16,24
    int b_k0 = tid >> 4;                 // 0..15 (and +16)
    int b_nc = (tid & 15) * 8;           // 0..120

    uint32_t sA0 = (uint32_t)__cvta_generic_to_shared(&sA[0][0]);
    uint32_t sA1 = (uint32_t)__cvta_generic_to_shared(&sA[1][0]);
    uint32_t sB0 = (uint32_t)__cvta_generic_to_shared(&sB[0][0]);
    uint32_t sB1 = (uint32_t)__cvta_generic_to_shared(&sB[1][0]);

    const int NIT = K >> 5;

    // issue loads for stage 'it' into buffer buf
    auto issue = [&](int it, uint32_t sAu, uint32_t sBu) {
        int k0 = it << 5;
        const __nv_bfloat16* Ag = A + (size_t)(rowBase + a_r0) * K + k0 + a_kc;
        cp16(sAu + (uint32_t)(a_r0 * SA_STRIDE + a_kc) * 2, Ag);
        cp16(sAu + (uint32_t)((a_r0 + 64) * SA_STRIDE + a_kc) * 2, Ag + (size_t)64 * K);
        const __nv_bfloat16* Bg = Bw + (size_t)(k0 + b_k0) * N + colBase + b_nc;
        cp16(sBu + (uint32_t)(b_k0 * SB_STRIDE + b_nc) * 2, Bg);
        cp16(sBu + (uint32_t)((b_k0 + 16) * SB_STRIDE + b_nc) * 2, Bg + (size_t)16 * N);
        asm volatile("cp.async.commit_group;\n" ::: "memory");
    };

    issue(0, sA0, sB0);
    if (NIT > 1) issue(1, sA1, sB1);

    float acc[2][8][4];
    #pragma unroll
    for (int i = 0; i < 2; i++)
        #pragma unroll
        for (int j = 0; j < 8; j++)
            #pragma unroll
            for (int t = 0; t < 4; t++) acc[i][j][t] = 0.f;

    int m0  = wy * 32;
    int n0w = wx * 64;
    int arow = lane & 15;
    int asel = (lane >> 4) << 3;

    for (int it = 0; it < NIT; it++) {
        if (it + 1 < NIT) asm volatile("cp.async.wait_group 1;\n" ::: "memory");
        else              asm volatile("cp.async.wait_group 0;\n" ::: "memory");
        __syncthreads();

        uint32_t sAu = (it & 1) ? sA1 : sA0;
        uint32_t sBu = (it & 1) ? sB1 : sB0;

        #pragma unroll
        for (int ks = 0; ks < 2; ks++) {
            int k0 = ks * 16;
            uint32_t a[2][4];
            #pragma unroll
            for (int mi = 0; mi < 2; mi++) {
                uint32_t addr = sAu + (uint32_t)((m0 + mi * 16 + arow) * SA_STRIDE + k0 + asel) * 2;
                ldsm_x4(a[mi][0], a[mi][1], a[mi][2], a[mi][3], addr);
            }
            uint32_t b[8][2];
            #pragma unroll
            for (int nj = 0; nj < 4; nj++) {
                uint32_t addr = sBu + (uint32_t)((k0 + (lane & 15)) * SB_STRIDE
                                                 + n0w + nj * 16 + ((lane >> 4) << 3)) * 2;
                ldsm_x4t(b[2 * nj][0], b[2 * nj][1], b[2 * nj + 1][0], b[2 * nj + 1][1], addr);
            }
            #pragma unroll
            for (int mi = 0; mi < 2; mi++)
                #pragma unroll
                for (int ni = 0; ni < 8; ni++)
                    mma_bf16(acc[mi][ni][0], acc[mi][ni][1], acc[mi][ni][2], acc[mi][ni][3],
                             a[mi][0], a[mi][1], a[mi][2], a[mi][3], b[ni][0], b[ni][1]);
        }
        __syncthreads();
        if (it + 2 < NIT) issue(it + 2, (it & 1) ? sA1 : sA0, (it & 1) ? sB1 : sB0);
    }

    // ---- epilogue ----
    int gr = lane >> 2, gc = (lane & 3) * 2;
    #pragma unroll
    for (int mi = 0; mi < 2; mi++) {
        #pragma unroll
        for (int ni = 0; ni < 8; ni++) {
            int col = colBase + n0w + ni * 8 + gc;
            float b0 = bias[col], b1 = bias[col + 1];
            #pragma unroll
            for (int half = 0; half < 2; half++) {
                size_t row = (size_t)(rowBase + m0 + mi * 16 + gr + half * 8);
                float v0 = acc[mi][ni][half * 2 + 0] + b0;
                float v1 = acc[mi][ni][half * 2 + 1] + b1;
                if (EPI == 2) {
                    v0 = 0.5f * v0 * (1.0f + erff(v0 * 0.70710678118654752f));
                    v1 = 0.5f * v1 * (1.0f + erff(v1 * 0.70710678118654752f));
                }
                if (EPI == 3) {
                    v0 += res[row * N + col];
                    v1 += res[row * N + col + 1];
                }
                if (EPI == 0 || EPI == 2) {
                    __nv_bfloat162* p = (__nv_bfloat162*)((__nv_bfloat16*)Cout + row * N + col);
                    *p = __floats2bfloat162_rn(v0, v1);
                } else {
                    float2* p = (float2*)((float*)Cout + row * N + col);
                    *p = make_float2(v0, v1);
                }
            }
        }
    }
}

// ---------------------------------------------------------------------------
extern "C" void kernel_launch(void* const* d_in, const int* in_sizes, int n_in,
                              void* d_out, int out_size) {
    const float* x      = (const float*)d_in[0];
    const float* n1g    = (const float*)d_in[1];
    const float* n1b    = (const float*)d_in[2];
    const float* qkv_w  = (const float*)d_in[3];
    const float* qkv_b  = (const float*)d_in[4];
    const float* proj_w = (const float*)d_in[5];
    const float* proj_b = (const float*)d_in[6];
    const float* rpb    = (const float*)d_in[7];
    const float* n2g    = (const float*)d_in[8];
    const float* n2b    = (const float*)d_in[9];
    const float* fc1_w  = (const float*)d_in[10];
    const float* fc1_b  = (const float*)d_in[11];
    const float* fc2_w  = (const float*)d_in[12];
    const float* fc2_b  = (const float*)d_in[13];
    float* out = (float*)d_out;

    __nv_bfloat16 *ln, *big, *attn, *wts;
    float *proj, *x1;
    cudaGetSymbolAddress((void**)&ln,   g_ln);
    cudaGetSymbolAddress((void**)&big,  g_big);
    cudaGetSymbolAddress((void**)&attn, g_attn);
    cudaGetSymbolAddress((void**)&proj, g_proj);
    cudaGetSymbolAddress((void**)&x1,   g_x1);
    cudaGetSymbolAddress((void**)&wts,  g_w);

    // 0) weights -> bf16
    k_f2bf<<<(196608 + 255) / 256, 256>>>(qkv_w,  wts + WOFF_QKV,  196608);
    k_f2bf<<<(65536  + 255) / 256, 256>>>(proj_w, wts + WOFF_PROJ, 65536);
    k_f2bf<<<(262144 + 255) / 256, 256>>>(fc1_w,  wts + WOFF_FC1,  262144);
    k_f2bf<<<(262144 + 255) / 256, 256>>>(fc2_w,  wts + WOFF_FC2,  262144);

    // 1) LN1 + roll + window partition -> ln (bf16, windowed)
    k_ln1_roll_part<<<Tv, 256>>>(x, n1g, n1b, ln);
    // 2) qkv GEMM -> big [T,768] bf16
    k_mmagemm<0><<<dim3(768 / 128, Tv / 128), 256>>>(ln, wts + WOFF_QKV, qkv_b, big, Tv, 768, 256, nullptr);
    // 3) fused windowed attention -> attn [T,256] bf16
    k_attn<<<BWIN * NHv, 128>>>(big, rpb, attn);
    // 4) proj GEMM -> proj [T,256] fp32
    k_mmagemm<1><<<dim3(256 / 128, Tv / 128), 256>>>(attn, wts + WOFF_PROJ, proj_b, proj, Tv, 256, 256, nullptr);
    // 5) x1 = x + reverse(roll back); LN2 -> x1 fp32, ln bf16 (natural)
    k_x1_ln2<<<Tv, 256>>>(x, proj, n2g, n2b, x1, ln);
    // 6) fc1 + GELU -> big [T,1024] bf16
    k_mmagemm<2><<<dim3(1024 / 128, Tv / 128), 256>>>(ln, wts + WOFF_FC1, fc1_b, big, Tv, 1024, 256, nullptr);
    // 7) fc2 + residual(x1) -> out fp32
    k_mmagemm<3><<<dim3(256 / 128, Tv / 128), 256>>>(big, wts + WOFF_FC2, fc2_b, out, Tv, 256, 1024, x1);
}

// round 3
// speedup vs baseline: 5.8230x; 1.7623x over previous
#include <cuda_runtime.h>
#include <cuda_bf16.h>
#include <math.h>
#include <stdint.h>

// Problem constants
#define Bv   2
#define Dv   16
#define Hv   56
#define Wv   56
#define Cv   256
#define NHv  8
#define HDv  32
#define WSv  4
#define SSv  2
#define NWIN 784           // windows per batch: 4*14*14
#define BWIN 1568          // total windows
#define Tv   100352        // total tokens  B*D*H*W

// ---------------------------------------------------------------------------
// Scratch (device globals; no allocation allowed)
__device__ __nv_bfloat16 g_ln[(size_t)Tv * 256];     // ln1 out (windowed) / ln2 out (natural)
__device__ __nv_bfloat16 g_big[(size_t)Tv * 1024];   // qkv out (768) / fc1 out (1024)
__device__ __nv_bfloat16 g_attn[(size_t)Tv * 256];   // attn out (windowed)
__device__ float         g_proj[(size_t)Tv * 256];   // proj out (windowed, fp32)
__device__ float         g_x1[(size_t)Tv * 256];     // x1 (natural, fp32)
__device__ __nv_bfloat16 g_w[786432];                // bf16 weights: qkv|proj|fc1|fc2

#define WOFF_QKV  0
#define WOFF_PROJ 196608
#define WOFF_FC1  262144
#define WOFF_FC2  524288
#define WTOTAL    786432

// ---------------------------------------------------------------------------
// All four weight conversions in one launch.
__global__ void k_f2bf4(const float* __restrict__ s0, const float* __restrict__ s1,
                        const float* __restrict__ s2, const float* __restrict__ s3,
                        __nv_bfloat16* __restrict__ dst) {
    int i = blockIdx.x * 256 + threadIdx.x;
    if (i >= WTOTAL) return;
    float v;
    if (i < WOFF_PROJ)      v = s0[i - WOFF_QKV];
    else if (i < WOFF_FC1)  v = s1[i - WOFF_PROJ];
    else if (i < WOFF_FC2)  v = s2[i - WOFF_FC1];
    else                    v = s3[i - WOFF_FC2];
    dst[i] = __float2bfloat16(v);
}

// ---------------------------------------------------------------------------
// Warp-wide LN: one warp per token, 8 channels per lane (float4 x2).
__device__ __forceinline__ void warp_ln8(const float* vin, float* vout,
                                         const float* __restrict__ g,
                                         const float* __restrict__ b, int cbase) {
    float s1 = 0.f, s2 = 0.f;
    #pragma unroll
    for (int t = 0; t < 8; t++) { s1 += vin[t]; s2 += vin[t] * vin[t]; }
    #pragma unroll
    for (int o = 16; o > 0; o >>= 1) {
        s1 += __shfl_xor_sync(0xffffffffu, s1, o);
        s2 += __shfl_xor_sync(0xffffffffu, s2, o);
    }
    float mu = s1 * (1.0f / 256.0f);
    float var = s2 * (1.0f / 256.0f) - mu * mu;
    float inv = rsqrtf(var + 1e-5f);
    float4 g0 = *(const float4*)(g + cbase);
    float4 g1 = *(const float4*)(g + cbase + 4);
    float4 b0 = *(const float4*)(b + cbase);
    float4 b1 = *(const float4*)(b + cbase + 4);
    vout[0] = (vin[0] - mu) * inv * g0.x + b0.x;
    vout[1] = (vin[1] - mu) * inv * g0.y + b0.y;
    vout[2] = (vin[2] - mu) * inv * g0.z + b0.z;
    vout[3] = (vin[3] - mu) * inv * g0.w + b0.w;
    vout[4] = (vin[4] - mu) * inv * g1.x + b1.x;
    vout[5] = (vin[5] - mu) * inv * g1.y + b1.y;
    vout[6] = (vin[6] - mu) * inv * g1.z + b1.z;
    vout[7] = (vin[7] - mu) * inv * g1.w + b1.w;
}

__device__ __forceinline__ uint4 pack8_bf16(const float* v) {
    uint4 r;
    __nv_bfloat162 p0 = __floats2bfloat162_rn(v[0], v[1]);
    __nv_bfloat162 p1 = __floats2bfloat162_rn(v[2], v[3]);
    __nv_bfloat162 p2 = __floats2bfloat162_rn(v[4], v[5]);
    __nv_bfloat162 p3 = __floats2bfloat162_rn(v[6], v[7]);
    r.x = *(uint32_t*)&p0; r.y = *(uint32_t*)&p1;
    r.z = *(uint32_t*)&p2; r.w = *(uint32_t*)&p3;
    return r;
}

// K1: LN1 + roll(-2) + window partition  ->  g_ln [BWIN*64, 256]  (bf16)
__global__ void __launch_bounds__(256) k_ln1_v2(
    const float* __restrict__ x, const float* __restrict__ g,
    const float* __restrict__ bta, __nv_bfloat16* __restrict__ out) {
    int wt = blockIdx.x * 8 + (threadIdx.x >> 5);    // windowed token
    int lane = threadIdx.x & 31;
    int i  = wt & 63, b_ = wt >> 6;
    int b = b_ / NWIN, widx = b_ % NWIN;
    int wd = widx / 196, r = widx % 196, wh = r / 14, ww = r % 14;
    int zi = i >> 4, yi = (i >> 2) & 3, xi = i & 3;
    int d = (wd * 4 + zi + SSv) & 15;
    int h = wh * 4 + yi + SSv; if (h >= Hv) h -= Hv;
    int w = ww * 4 + xi + SSv; if (w >= Wv) w -= Wv;
    const float* row = x + ((size_t)((b * Dv + d) * Hv + h) * Wv + w) * Cv + lane * 8;
    float vin[8], vo[8];
    *(float4*)vin     = *(const float4*)row;
    *(float4*)(vin+4) = *(const float4*)(row + 4);
    warp_ln8(vin, vo, g, bta, lane * 8);
    *(uint4*)(out + (size_t)wt * Cv + lane * 8) = pack8_bf16(vo);
}

// K5: x1 = x + reverse(roll(proj_out)),  then LN2
__global__ void __launch_bounds__(256) k_x1_ln2_v2(
    const float* __restrict__ x, const float* __restrict__ projout,
    const float* __restrict__ g, const float* __restrict__ bta,
    float* __restrict__ x1, __nv_bfloat16* __restrict__ lnout) {
    int t = blockIdx.x * 8 + (threadIdx.x >> 5);     // natural token
    int lane = threadIdx.x & 31;
    int w = t % Wv, tmp = t / Wv;
    int h = tmp % Hv; tmp /= Hv;
    int d = tmp % Dv; int b = tmp / Dv;
    int ds = (d - SSv) & 15;
    int hs = h - SSv; if (hs < 0) hs += Hv;
    int ws = w - SSv; if (ws < 0) ws += Wv;
    int wt = ((b * NWIN + (ds >> 2) * 196 + (hs >> 2) * 14 + (ws >> 2)) << 6)
             + ((ds & 3) << 4) + ((hs & 3) << 2) + (ws & 3);
    const float* xr = x + (size_t)t * Cv + lane * 8;
    const float* pr = projout + (size_t)wt * Cv + lane * 8;
    float vin[8], vo[8];
    #pragma unroll
    for (int k = 0; k < 8; k += 4) {
        float4 a = *(const float4*)(xr + k);
        float4 c = *(const float4*)(pr + k);
        vin[k] = a.x + c.x; vin[k+1] = a.y + c.y; vin[k+2] = a.z + c.z; vin[k+3] = a.w + c.w;
    }
    float* x1r = x1 + (size_t)t * Cv + lane * 8;
    *(float4*)x1r       = *(float4*)vin;
    *(float4*)(x1r + 4) = *(float4*)(vin + 4);
    warp_ln8(vin, vo, g, bta, lane * 8);
    *(uint4*)(lnout + (size_t)t * Cv + lane * 8) = pack8_bf16(vo);
}

// ---------------------------------------------------------------------------
// MMA primitives
__device__ __forceinline__ void ldsm_x4(uint32_t& r0, uint32_t& r1, uint32_t& r2, uint32_t& r3,
                                        uint32_t addr) {
    asm volatile("ldmatrix.sync.aligned.m8n8.x4.shared.b16 {%0,%1,%2,%3}, [%4];\n"
                 : "=r"(r0), "=r"(r1), "=r"(r2), "=r"(r3) : "r"(addr));
}
__device__ __forceinline__ void ldsm_x4t(uint32_t& r0, uint32_t& r1, uint32_t& r2, uint32_t& r3,
                                         uint32_t addr) {
    asm volatile("ldmatrix.sync.aligned.m8n8.x4.trans.shared.b16 {%0,%1,%2,%3}, [%4];\n"
                 : "=r"(r0), "=r"(r1), "=r"(r2), "=r"(r3) : "r"(addr));
}
__device__ __forceinline__ void mma_bf16(float& d0, float& d1, float& d2, float& d3,
                                         uint32_t a0, uint32_t a1, uint32_t a2, uint32_t a3,
                                         uint32_t b0, uint32_t b1) {
    asm volatile("mma.sync.aligned.m16n8k16.row.col.f32.bf16.bf16.f32 "
                 "{%0,%1,%2,%3}, {%4,%5,%6,%7}, {%8,%9}, {%0,%1,%2,%3};\n"
                 : "+f"(d0), "+f"(d1), "+f"(d2), "+f"(d3)
                 : "r"(a0), "r"(a1), "r"(a2), "r"(a3), "r"(b0), "r"(b1));
}
__device__ __forceinline__ void cp16(uint32_t dst, const void* src) {
    asm volatile("cp.async.cg.shared.global [%0], [%1], 16;\n" :: "r"(dst), "l"(src));
}

// ---------------------------------------------------------------------------
// K3: tensor-core windowed attention. One block per window, 8 warps = 8 heads.
// Smem: Q/K/V per head [64 rows x 40 bf16] (32 used) + rpb table + labels.
#define ATT_STRIDE 40
#define ATT_MAT    (64 * ATT_STRIDE)        // 2560 bf16 per matrix per head
#define ATT_SMEM   (3 * 8 * ATT_MAT * 2 + 2744 * 4 + 64 * 4)

extern __shared__ char att_smem[];

__global__ void __launch_bounds__(256) k_attn_mma(
    const __nv_bfloat16* __restrict__ qkv, const float* __restrict__ rpb,
    __nv_bfloat16* __restrict__ out) {
    int b_   = blockIdx.x;
    int tid  = threadIdx.x;
    int lane = tid & 31;
    int h    = tid >> 5;

    __nv_bfloat16* smQ = (__nv_bfloat16*)att_smem;
    __nv_bfloat16* smK = smQ + 8 * ATT_MAT;
    __nv_bfloat16* smV = smK + 8 * ATT_MAT;
    float* rpb_s  = (float*)(smV + 8 * ATT_MAT);
    int*   label_s = (int*)(rpb_s + 2744);

    uint32_t sq = (uint32_t)__cvta_generic_to_shared(smQ + h * ATT_MAT);
    uint32_t sk = (uint32_t)__cvta_generic_to_shared(smK + h * ATT_MAT);
    uint32_t sv = (uint32_t)__cvta_generic_to_shared(smV + h * ATT_MAT);

    // per-warp QKV loads (each warp its own head)
    const __nv_bfloat16* base = qkv + (size_t)b_ * 64 * 768 + h * HDv;
    #pragma unroll
    for (int c = 0; c < 8; c++) {
        int idx = c * 32 + lane;                // 0..255
        int row = idx >> 2, grp = (idx & 3) * 8;
        const __nv_bfloat16* gp = base + (size_t)row * 768 + grp;
        uint32_t off = (uint32_t)(row * ATT_STRIDE + grp) * 2;
        cp16(sq + off, gp);
        cp16(sk + off, gp + 256);
        cp16(sv + off, gp + 512);
    }
    asm volatile("cp.async.commit_group;\n" ::: "memory");

    // cooperative: rpb table + labels
    for (int i = tid; i < 2744; i += 256) rpb_s[i] = rpb[i];
    if (tid < 64) {
        int widx = b_ % NWIN;
        int wd = widx / 196, rr = widx % 196, wh = rr / 14, ww = rr % 14;
        int zi = tid >> 4, yi = (tid >> 2) & 3, xi = tid & 3;
        int dg = wd * 4 + zi, hg = wh * 4 + yi, wg = ww * 4 + xi;
        int rd = dg < Dv - WSv ? 0 : (dg < Dv - SSv ? 1 : 2);
        int rh = hg < Hv - WSv ? 0 : (hg < Hv - SSv ? 1 : 2);
        int rw = wg < Wv - WSv ? 0 : (wg < Wv - SSv ? 1 : 2);
        label_s[tid] = rd * 9 + rh * 3 + rw;
    }
    asm volatile("cp.async.wait_group 0;\n" ::: "memory");
    __syncthreads();

    // ---- S = Q K^T  (64x64, K=32) ----
    float acc[4][8][4];
    #pragma unroll
    for (int a = 0; a < 4; a++)
        #pragma unroll
        for (int bq = 0; bq < 8; bq++)
            #pragma unroll
            for (int t = 0; t < 4; t++) acc[a][bq][t] = 0.f;

    int arow = lane & 15;
    int asel = (lane >> 4) << 3;
    int br   = (lane & 7) + ((lane >> 4) << 3);
    int bkh  = ((lane >> 3) & 1) << 3;

    #pragma unroll
    for (int ks = 0; ks < 2; ks++) {
        int k0 = ks * 16;
        uint32_t af[4][4];
        #pragma unroll
        for (int mi = 0; mi < 4; mi++)
            ldsm_x4(af[mi][0], af[mi][1], af[mi][2], af[mi][3],
                    sq + (uint32_t)((mi * 16 + arow) * ATT_STRIDE + k0 + asel) * 2);
        uint32_t bf[8][2];
        #pragma unroll
        for (int nb = 0; nb < 4; nb++)
            ldsm_x4(bf[2*nb][0], bf[2*nb][1], bf[2*nb+1][0], bf[2*nb+1][1],
                    sk + (uint32_t)((nb * 16 + br) * ATT_STRIDE + k0 + bkh) * 2);
        #pragma unroll
        for (int mi = 0; mi < 4; mi++)
            #pragma unroll
            for (int nj = 0; nj < 8; nj++)
                mma_bf16(acc[mi][nj][0], acc[mi][nj][1], acc[mi][nj][2], acc[mi][nj][3],
                         af[mi][0], af[mi][1], af[mi][2], af[mi][3], bf[nj][0], bf[nj][1]);
    }

    // ---- bias + mask + softmax (registers) ----
    int r0 = lane >> 2;          // row within 8-row group
    int cq = (lane & 3) * 2;     // col pair base
    int ui[8], li[8];
    #pragma unroll
    for (int mi = 0; mi < 4; mi++)
        #pragma unroll
        for (int hh = 0; hh < 2; hh++) {
            int i = mi * 16 + hh * 8 + r0;
            ui[mi * 2 + hh] = 49 * (i >> 4) + 7 * ((i >> 2) & 3) + (i & 3);
            li[mi * 2 + hh] = label_s[i];
        }
    int uj[16], lj[16];
    #pragma unroll
    for (int nj = 0; nj < 8; nj++)
        #pragma unroll
        for (int t = 0; t < 2; t++) {
            int j = nj * 8 + cq + t;
            uj[nj * 2 + t] = 49 * (j >> 4) + 7 * ((j >> 2) & 3) + (j & 3);
            lj[nj * 2 + t] = label_s[j];
        }

    const float scale = 0.17677669529663689f;
    #pragma unroll
    for (int mi = 0; mi < 4; mi++)
        #pragma unroll
        for (int nj = 0; nj < 8; nj++)
            #pragma unroll
            for (int hh = 0; hh < 2; hh++)
                #pragma unroll
                for (int t = 0; t < 2; t++) {
                    float s = acc[mi][nj][hh * 2 + t] * scale;
                    int idx = 171 + ui[mi * 2 + hh] - uj[nj * 2 + t];
                    s += rpb_s[idx * NHv + h];
                    if (li[mi * 2 + hh] != lj[nj * 2 + t]) s -= 100.0f;
                    acc[mi][nj][hh * 2 + t] = s;
                }

    float invs[4][2];
    #pragma unroll
    for (int mi = 0; mi < 4; mi++)
        #pragma unroll
        for (int hh = 0; hh < 2; hh++) {
            float m = -1e30f;
            #pragma unroll
            for (int nj = 0; nj < 8; nj++) {
                m = fmaxf(m, acc[mi][nj][hh * 2]);
                m = fmaxf(m, acc[mi][nj][hh * 2 + 1]);
            }
            m = fmaxf(m, __shfl_xor_sync(0xffffffffu, m, 1));
            m = fmaxf(m, __shfl_xor_sync(0xffffffffu, m, 2));
            float sum = 0.f;
            #pragma unroll
            for (int nj = 0; nj < 8; nj++) {
                float e0 = __expf(acc[mi][nj][hh * 2]     - m);
                float e1 = __expf(acc[mi][nj][hh * 2 + 1] - m);
                acc[mi][nj][hh * 2] = e0; acc[mi][nj][hh * 2 + 1] = e1;
                sum += e0 + e1;
            }
            sum += __shfl_xor_sync(0xffffffffu, sum, 1);
            sum += __shfl_xor_sync(0xffffffffu, sum, 2);
            invs[mi][hh] = 1.0f / sum;
        }

    // pack P to bf16 A-fragments
    uint32_t pk[4][8][2];
    #pragma unroll
    for (int mi = 0; mi < 4; mi++)
        #pragma unroll
        for (int t = 0; t < 8; t++) {
            __nv_bfloat162 p0 = __floats2bfloat162_rn(acc[mi][t][0] * invs[mi][0],
                                                      acc[mi][t][1] * invs[mi][0]);
            __nv_bfloat162 p1 = __floats2bfloat162_rn(acc[mi][t][2] * invs[mi][1],
                                                      acc[mi][t][3] * invs[mi][1]);
            pk[mi][t][0] = *(uint32_t*)&p0;
            pk[mi][t][1] = *(uint32_t*)&p1;
        }

    // ---- O = P V  (64x32, K=64) ----
    float o[4][4][4];
    #pragma unroll
    for (int a = 0; a < 4; a++)
        #pragma unroll
        for (int bq = 0; bq < 4; bq++)
            #pragma unroll
            for (int t = 0; t < 4; t++) o[a][bq][t] = 0.f;

    #pragma unroll
    for (int kt = 0; kt < 4; kt++) {
        uint32_t bv[4][2];
        #pragma unroll
        for (int nb = 0; nb < 2; nb++)
            ldsm_x4t(bv[2*nb][0], bv[2*nb][1], bv[2*nb+1][0], bv[2*nb+1][1],
                     sv + (uint32_t)((kt * 16 + arow) * ATT_STRIDE + nb * 16 + asel) * 2);
        #pragma unroll
        for (int mi = 0; mi < 4; mi++)
            #pragma unroll
            for (int nt = 0; nt < 4; nt++)
                mma_bf16(o[mi][nt][0], o[mi][nt][1], o[mi][nt][2], o[mi][nt][3],
                         pk[mi][2*kt][0], pk[mi][2*kt][1], pk[mi][2*kt+1][0], pk[mi][2*kt+1][1],
                         bv[nt][0], bv[nt][1]);
    }

    // ---- store O (bf16) ----
    #pragma unroll
    for (int mi = 0; mi < 4; mi++)
        #pragma unroll
        for (int nt = 0; nt < 4; nt++)
            #pragma unroll
            for (int hh = 0; hh < 2; hh++) {
                int row = mi * 16 + hh * 8 + r0;
                int col = h * HDv + nt * 8 + cq;
                __nv_bfloat162 p = __floats2bfloat162_rn(o[mi][nt][hh * 2],
                                                         o[mi][nt][hh * 2 + 1]);
                *(__nv_bfloat162*)(out + ((size_t)b_ * 64 + row) * Cv + col) = p;
            }
}

// ---------------------------------------------------------------------------
// bf16 tensor-core GEMM: C[M,N] = A[M,K] @ B[K,N] + bias (+epilogue)
// BM=128, BN=128, BK=32, 256 threads (8 warps, 4x2), warp tile 32x64.
// EPI: 0 = bf16 out, 1 = fp32 out, 2 = GELU + bf16 out, 3 = +res, fp32 out
#define SA_STRIDE 40
#define SB_STRIDE 136

template<int EPI>
__global__ void __launch_bounds__(256) k_mmagemm(
    const __nv_bfloat16* __restrict__ A, const __nv_bfloat16* __restrict__ Bw,
    const float* __restrict__ bias, void* __restrict__ Cout,
    int M, int N, int K, const float* __restrict__ res) {
    __shared__ __nv_bfloat16 sA[2][128 * SA_STRIDE];
    __shared__ __nv_bfloat16 sB[2][32 * SB_STRIDE];

    int tid  = threadIdx.x;
    int lane = tid & 31, warp = tid >> 5;
    int wy = warp >> 1, wx = warp & 1;
    int rowBase = blockIdx.y * 128;
    int colBase = blockIdx.x * 128;

    int a_r0 = tid >> 2;
    int a_kc = (tid & 3) * 8;
    int b_k0 = tid >> 4;
    int b_nc = (tid & 15) * 8;

    uint32_t sA0 = (uint32_t)__cvta_generic_to_shared(&sA[0][0]);
    uint32_t sA1 = (uint32_t)__cvta_generic_to_shared(&sA[1][0]);
    uint32_t sB0 = (uint32_t)__cvta_generic_to_shared(&sB[0][0]);
    uint32_t sB1 = (uint32_t)__cvta_generic_to_shared(&sB[1][0]);

    const int NIT = K >> 5;

    auto issue = [&](int it, uint32_t sAu, uint32_t sBu) {
        int k0 = it << 5;
        const __nv_bfloat16* Ag = A + (size_t)(rowBase + a_r0) * K + k0 + a_kc;
        cp16(sAu + (uint32_t)(a_r0 * SA_STRIDE + a_kc) * 2, Ag);
        cp16(sAu + (uint32_t)((a_r0 + 64) * SA_STRIDE + a_kc) * 2, Ag + (size_t)64 * K);
        const __nv_bfloat16* Bg = Bw + (size_t)(k0 + b_k0) * N + colBase + b_nc;
        cp16(sBu + (uint32_t)(b_k0 * SB_STRIDE + b_nc) * 2, Bg);
        cp16(sBu + (uint32_t)((b_k0 + 16) * SB_STRIDE + b_nc) * 2, Bg + (size_t)16 * N);
        asm volatile("cp.async.commit_group;\n" ::: "memory");
    };

    issue(0, sA0, sB0);
    if (NIT > 1) issue(1, sA1, sB1);

    float acc[2][8][4];
    #pragma unroll
    for (int i = 0; i < 2; i++)
        #pragma unroll
        for (int j = 0; j < 8; j++)
            #pragma unroll
            for (int t = 0; t < 4; t++) acc[i][j][t] = 0.f;

    int m0  = wy * 32;
    int n0w = wx * 64;
    int arow = lane & 15;
    int asel = (lane >> 4) << 3;

    for (int it = 0; it < NIT; it++) {
        if (it + 1 < NIT) asm volatile("cp.async.wait_group 1;\n" ::: "memory");
        else              asm volatile("cp.async.wait_group 0;\n" ::: "memory");
        __syncthreads();

        uint32_t sAu = (it & 1) ? sA1 : sA0;
        uint32_t sBu = (it & 1) ? sB1 : sB0;

        #pragma unroll
        for (int ks = 0; ks < 2; ks++) {
            int k0 = ks * 16;
            uint32_t a[2][4];
            #pragma unroll
            for (int mi = 0; mi < 2; mi++)
                ldsm_x4(a[mi][0], a[mi][1], a[mi][2], a[mi][3],
                        sAu + (uint32_t)((m0 + mi * 16 + arow) * SA_STRIDE + k0 + asel) * 2);
            uint32_t b[8][2];
            #pragma unroll
            for (int nj = 0; nj < 4; nj++)
                ldsm_x4t(b[2 * nj][0], b[2 * nj][1], b[2 * nj + 1][0], b[2 * nj + 1][1],
                         sBu + (uint32_t)((k0 + (lane & 15)) * SB_STRIDE
                                          + n0w + nj * 16 + ((lane >> 4) << 3)) * 2);
            #pragma unroll
            for (int mi = 0; mi < 2; mi++)
                #pragma unroll
                for (int ni = 0; ni < 8; ni++)
                    mma_bf16(acc[mi][ni][0], acc[mi][ni][1], acc[mi][ni][2], acc[mi][ni][3],
                             a[mi][0], a[mi][1], a[mi][2], a[mi][3], b[ni][0], b[ni][1]);
        }
        __syncthreads();
        if (it + 2 < NIT) issue(it + 2, (it & 1) ? sA1 : sA0, (it & 1) ? sB1 : sB0);
    }

    int gr = lane >> 2, gc = (lane & 3) * 2;
    #pragma unroll
    for (int mi = 0; mi < 2; mi++) {
        #pragma unroll
        for (int ni = 0; ni < 8; ni++) {
            int col = colBase + n0w + ni * 8 + gc;
            float b0 = bias[col], b1 = bias[col + 1];
            #pragma unroll
            for (int half = 0; half < 2; half++) {
                size_t row = (size_t)(rowBase + m0 + mi * 16 + gr + half * 8);
                float v0 = acc[mi][ni][half * 2 + 0] + b0;
                float v1 = acc[mi][ni][half * 2 + 1] + b1;
                if (EPI == 2) {
                    v0 = 0.5f * v0 * (1.0f + erff(v0 * 0.70710678118654752f));
                    v1 = 0.5f * v1 * (1.0f + erff(v1 * 0.70710678118654752f));
                }
                if (EPI == 3) {
                    v0 += res[row * N + col];
                    v1 += res[row * N + col + 1];
                }
                if (EPI == 0 || EPI == 2) {
                    __nv_bfloat162* p = (__nv_bfloat162*)((__nv_bfloat16*)Cout + row * N + col);
                    *p = __floats2bfloat162_rn(v0, v1);
                } else {
                    float2* p = (float2*)((float*)Cout + row * N + col);
                    *p = make_float2(v0, v1);
                }
            }
        }
    }
}

// ---------------------------------------------------------------------------
extern "C" void kernel_launch(void* const* d_in, const int* in_sizes, int n_in,
                              void* d_out, int out_size) {
    const float* x      = (const float*)d_in[0];
    const float* n1g    = (const float*)d_in[1];
    const float* n1b    = (const float*)d_in[2];
    const float* qkv_w  = (const float*)d_in[3];
    const float* qkv_b  = (const float*)d_in[4];
    const float* proj_w = (const float*)d_in[5];
    const float* proj_b = (const float*)d_in[6];
    const float* rpb    = (const float*)d_in[7];
    const float* n2g    = (const float*)d_in[8];
    const float* n2b    = (const float*)d_in[9];
    const float* fc1_w  = (const float*)d_in[10];
    const float* fc1_b  = (const float*)d_in[11];
    const float* fc2_w  = (const float*)d_in[12];
    const float* fc2_b  = (const float*)d_in[13];
    float* out = (float*)d_out;

    __nv_bfloat16 *ln, *big, *attn, *wts;
    float *proj, *x1;
    cudaGetSymbolAddress((void**)&ln,   g_ln);
    cudaGetSymbolAddress((void**)&big,  g_big);
    cudaGetSymbolAddress((void**)&attn, g_attn);
    cudaGetSymbolAddress((void**)&proj, g_proj);
    cudaGetSymbolAddress((void**)&x1,   g_x1);
    cudaGetSymbolAddress((void**)&wts,  g_w);

    cudaFuncSetAttribute(k_attn_mma, cudaFuncAttributeMaxDynamicSharedMemorySize, ATT_SMEM);

    // 0) weights -> bf16 (one launch)
    k_f2bf4<<<(WTOTAL + 255) / 256, 256>>>(qkv_w, proj_w, fc1_w, fc2_w, wts);

    // 1) LN1 + roll + window partition -> ln (bf16, windowed)
    k_ln1_v2<<<Tv / 8, 256>>>(x, n1g, n1b, ln);
    // 2) qkv GEMM -> big [T,768] bf16
    k_mmagemm<0><<<dim3(768 / 128, Tv / 128), 256>>>(ln, wts + WOFF_QKV, qkv_b, big, Tv, 768, 256, nullptr);
    // 3) tensor-core windowed attention -> attn [T,256] bf16
    k_attn_mma<<<BWIN, 256, ATT_SMEM>>>(big, rpb, attn);
    // 4) proj GEMM -> proj [T,256] fp32
    k_mmagemm<1><<<dim3(256 / 128, Tv / 128), 256>>>(attn, wts + WOFF_PROJ, proj_b, proj, Tv, 256, 256, nullptr);
    // 5) x1 = x + reverse(roll back); LN2
    k_x1_ln2_v2<<<Tv / 8, 256>>>(x, proj, n2g, n2b, x1, ln);
    // 6) fc1 + GELU -> big [T,1024] bf16
    k_mmagemm<2><<<dim3(1024 / 128, Tv / 128), 256>>>(ln, wts + WOFF_FC1, fc1_b, big, Tv, 1024, 256, nullptr);
    // 7) fc2 + residual(x1) -> out fp32
    k_mmagemm<3><<<dim3(256 / 128, Tv / 128), 256>>>(big, wts + WOFF_FC2, fc2_b, out, Tv, 256, 1024, x1);
}

// round 4
// speedup vs baseline: 6.0232x; 1.0344x over previous
#include <cuda_runtime.h>
#include <cuda_bf16.h>
#include <math.h>
#include <stdint.h>

// Problem constants
#define Bv   2
#define Dv   16
#define Hv   56
#define Wv   56
#define Cv   256
#define NHv  8
#define HDv  32
#define WSv  4
#define SSv  2
#define NWIN 784
#define BWIN 1568
#define Tv   100352

// ---------------------------------------------------------------------------
// Scratch (device globals; no allocation allowed)
__device__ __nv_bfloat16 g_ln[(size_t)Tv * 256];
__device__ __nv_bfloat16 g_big[(size_t)Tv * 1024];
__device__ __nv_bfloat16 g_attn[(size_t)Tv * 256];
__device__ float         g_proj[(size_t)Tv * 256];
__device__ float         g_x1[(size_t)Tv * 256];
__device__ __nv_bfloat16 g_w[786432];

#define WOFF_QKV  0
#define WOFF_PROJ 196608
#define WOFF_FC1  262144
#define WOFF_FC2  524288
#define WTOTAL    786432

// ---------------------------------------------------------------------------
__global__ void k_f2bf4(const float* __restrict__ s0, const float* __restrict__ s1,
                        const float* __restrict__ s2, const float* __restrict__ s3,
                        __nv_bfloat16* __restrict__ dst) {
    int i = blockIdx.x * 256 + threadIdx.x;
    if (i >= WTOTAL) return;
    float v;
    if (i < WOFF_PROJ)      v = s0[i - WOFF_QKV];
    else if (i < WOFF_FC1)  v = s1[i - WOFF_PROJ];
    else if (i < WOFF_FC2)  v = s2[i - WOFF_FC1];
    else                    v = s3[i - WOFF_FC2];
    dst[i] = __float2bfloat16(v);
}

// ---------------------------------------------------------------------------
// Warp-wide LN: one warp per token, 8 channels per lane.
__device__ __forceinline__ void warp_ln8(const float* vin, float* vout,
                                         const float* __restrict__ g,
                                         const float* __restrict__ b, int cbase) {
    float s1 = 0.f, s2 = 0.f;
    #pragma unroll
    for (int t = 0; t < 8; t++) { s1 += vin[t]; s2 += vin[t] * vin[t]; }
    #pragma unroll
    for (int o = 16; o > 0; o >>= 1) {
        s1 += __shfl_xor_sync(0xffffffffu, s1, o);
        s2 += __shfl_xor_sync(0xffffffffu, s2, o);
    }
    float mu = s1 * (1.0f / 256.0f);
    float var = s2 * (1.0f / 256.0f) - mu * mu;
    float inv = rsqrtf(var + 1e-5f);
    float4 g0 = *(const float4*)(g + cbase);
    float4 g1 = *(const float4*)(g + cbase + 4);
    float4 b0 = *(const float4*)(b + cbase);
    float4 b1 = *(const float4*)(b + cbase + 4);
    vout[0] = (vin[0] - mu) * inv * g0.x + b0.x;
    vout[1] = (vin[1] - mu) * inv * g0.y + b0.y;
    vout[2] = (vin[2] - mu) * inv * g0.z + b0.z;
    vout[3] = (vin[3] - mu) * inv * g0.w + b0.w;
    vout[4] = (vin[4] - mu) * inv * g1.x + b1.x;
    vout[5] = (vin[5] - mu) * inv * g1.y + b1.y;
    vout[6] = (vin[6] - mu) * inv * g1.z + b1.z;
    vout[7] = (vin[7] - mu) * inv * g1.w + b1.w;
}

__device__ __forceinline__ uint4 pack8_bf16(const float* v) {
    uint4 r;
    __nv_bfloat162 p0 = __floats2bfloat162_rn(v[0], v[1]);
    __nv_bfloat162 p1 = __floats2bfloat162_rn(v[2], v[3]);
    __nv_bfloat162 p2 = __floats2bfloat162_rn(v[4], v[5]);
    __nv_bfloat162 p3 = __floats2bfloat162_rn(v[6], v[7]);
    r.x = *(uint32_t*)&p0; r.y = *(uint32_t*)&p1;
    r.z = *(uint32_t*)&p2; r.w = *(uint32_t*)&p3;
    return r;
}

__global__ void __launch_bounds__(256) k_ln1_v2(
    const float* __restrict__ x, const float* __restrict__ g,
    const float* __restrict__ bta, __nv_bfloat16* __restrict__ out) {
    int wt = blockIdx.x * 8 + (threadIdx.x >> 5);
    int lane = threadIdx.x & 31;
    int i  = wt & 63, b_ = wt >> 6;
    int b = b_ / NWIN, widx = b_ % NWIN;
    int wd = widx / 196, r = widx % 196, wh = r / 14, ww = r % 14;
    int zi = i >> 4, yi = (i >> 2) & 3, xi = i & 3;
    int d = (wd * 4 + zi + SSv) & 15;
    int h = wh * 4 + yi + SSv; if (h >= Hv) h -= Hv;
    int w = ww * 4 + xi + SSv; if (w >= Wv) w -= Wv;
    const float* row = x + ((size_t)((b * Dv + d) * Hv + h) * Wv + w) * Cv + lane * 8;
    float vin[8], vo[8];
    *(float4*)vin     = *(const float4*)row;
    *(float4*)(vin+4) = *(const float4*)(row + 4);
    warp_ln8(vin, vo, g, bta, lane * 8);
    *(uint4*)(out + (size_t)wt * Cv + lane * 8) = pack8_bf16(vo);
}

__global__ void __launch_bounds__(256) k_x1_ln2_v2(
    const float* __restrict__ x, const float* __restrict__ projout,
    const float* __restrict__ g, const float* __restrict__ bta,
    float* __restrict__ x1, __nv_bfloat16* __restrict__ lnout) {
    int t = blockIdx.x * 8 + (threadIdx.x >> 5);
    int lane = threadIdx.x & 31;
    int w = t % Wv, tmp = t / Wv;
    int h = tmp % Hv; tmp /= Hv;
    int d = tmp % Dv; int b = tmp / Dv;
    int ds = (d - SSv) & 15;
    int hs = h - SSv; if (hs < 0) hs += Hv;
    int ws = w - SSv; if (ws < 0) ws += Wv;
    int wt = ((b * NWIN + (ds >> 2) * 196 + (hs >> 2) * 14 + (ws >> 2)) << 6)
             + ((ds & 3) << 4) + ((hs & 3) << 2) + (ws & 3);
    const float* xr = x + (size_t)t * Cv + lane * 8;
    const float* pr = projout + (size_t)wt * Cv + lane * 8;
    float vin[8], vo[8];
    #pragma unroll
    for (int k = 0; k < 8; k += 4) {
        float4 a = *(const float4*)(xr + k);
        float4 c = *(const float4*)(pr + k);
        vin[k] = a.x + c.x; vin[k+1] = a.y + c.y; vin[k+2] = a.z + c.z; vin[k+3] = a.w + c.w;
    }
    float* x1r = x1 + (size_t)t * Cv + lane * 8;
    *(float4*)x1r       = *(float4*)vin;
    *(float4*)(x1r + 4) = *(float4*)(vin + 4);
    warp_ln8(vin, vo, g, bta, lane * 8);
    *(uint4*)(lnout + (size_t)t * Cv + lane * 8) = pack8_bf16(vo);
}

// ---------------------------------------------------------------------------
// MMA primitives
__device__ __forceinline__ void ldsm_x4(uint32_t& r0, uint32_t& r1, uint32_t& r2, uint32_t& r3,
                                        uint32_t addr) {
    asm volatile("ldmatrix.sync.aligned.m8n8.x4.shared.b16 {%0,%1,%2,%3}, [%4];\n"
                 : "=r"(r0), "=r"(r1), "=r"(r2), "=r"(r3) : "r"(addr));
}
__device__ __forceinline__ void ldsm_x4t(uint32_t& r0, uint32_t& r1, uint32_t& r2, uint32_t& r3,
                                         uint32_t addr) {
    asm volatile("ldmatrix.sync.aligned.m8n8.x4.trans.shared.b16 {%0,%1,%2,%3}, [%4];\n"
                 : "=r"(r0), "=r"(r1), "=r"(r2), "=r"(r3) : "r"(addr));
}
__device__ __forceinline__ void mma_bf16(float& d0, float& d1, float& d2, float& d3,
                                         uint32_t a0, uint32_t a1, uint32_t a2, uint32_t a3,
                                         uint32_t b0, uint32_t b1) {
    asm volatile("mma.sync.aligned.m16n8k16.row.col.f32.bf16.bf16.f32 "
                 "{%0,%1,%2,%3}, {%4,%5,%6,%7}, {%8,%9}, {%0,%1,%2,%3};\n"
                 : "+f"(d0), "+f"(d1), "+f"(d2), "+f"(d3)
                 : "r"(a0), "r"(a1), "r"(a2), "r"(a3), "r"(b0), "r"(b1));
}
__device__ __forceinline__ void cp16(uint32_t dst, const void* src) {
    asm volatile("cp.async.cg.shared.global [%0], [%1], 16;\n" :: "r"(dst), "l"(src));
}

// ---------------------------------------------------------------------------
// K3: tensor-core windowed attention. Block = 4 heads of one window,
// 8 warps (2 per head), 256 threads. grid = BWIN*2.
#define ATT_STRIDE 40
#define ATT_MAT    (64 * ATT_STRIDE)                    // 2560 bf16
#define ATT_SMEM   (3 * 4 * ATT_MAT * 2 + 1372 * 4 + 64 * 4)

extern __shared__ char dyn_smem[];

__global__ void __launch_bounds__(256, 2) k_attn_mma(
    const __nv_bfloat16* __restrict__ qkv, const float* __restrict__ rpb,
    __nv_bfloat16* __restrict__ out) {
    int wnd  = blockIdx.x >> 1;
    int half = blockIdx.x & 1;
    int tid  = threadIdx.x;
    int lane = tid & 31;
    int warp = tid >> 5;
    int hl   = warp >> 1;          // local head 0..3
    int sub  = warp & 1;           // row-half of the head
    int head = half * 4 + hl;

    __nv_bfloat16* smQ = (__nv_bfloat16*)dyn_smem;
    __nv_bfloat16* smK = smQ + 4 * ATT_MAT;
    __nv_bfloat16* smV = smK + 4 * ATT_MAT;
    float* rpb_s   = (float*)(smV + 4 * ATT_MAT);       // [343][4]
    int*   label_s = (int*)(rpb_s + 1372);

    uint32_t sq = (uint32_t)__cvta_generic_to_shared(smQ + hl * ATT_MAT);
    uint32_t sk = (uint32_t)__cvta_generic_to_shared(smK + hl * ATT_MAT);
    uint32_t sv = (uint32_t)__cvta_generic_to_shared(smV + hl * ATT_MAT);

    // QKV loads: 2 warps (64 threads) per head, 4 chunks each.
    const __nv_bfloat16* base = qkv + (size_t)wnd * 64 * 768 + head * HDv;
    #pragma unroll
    for (int c = 0; c < 4; c++) {
        int idx = c * 64 + sub * 32 + lane;      // 0..255
        int row = idx >> 2, grp = (idx & 3) * 8;
        const __nv_bfloat16* gp = base + (size_t)row * 768 + grp;
        uint32_t off = (uint32_t)(row * ATT_STRIDE + grp) * 2;
        cp16(sq + off, gp);
        cp16(sk + off, gp + 256);
        cp16(sv + off, gp + 512);
    }
    asm volatile("cp.async.commit_group;\n" ::: "memory");

    // rpb slice for this block's 4 heads + labels
    for (int i = tid; i < 1372; i += 256)
        rpb_s[i] = rpb[(i >> 2) * NHv + half * 4 + (i & 3)];
    if (tid < 64) {
        int widx = wnd % NWIN;
        int wd = widx / 196, rr = widx % 196, wh = rr / 14, ww = rr % 14;
        int zi = tid >> 4, yi = (tid >> 2) & 3, xi = tid & 3;
        int dg = wd * 4 + zi, hg = wh * 4 + yi, wg = ww * 4 + xi;
        int rd = dg < Dv - WSv ? 0 : (dg < Dv - SSv ? 1 : 2);
        int rh = hg < Hv - WSv ? 0 : (hg < Hv - SSv ? 1 : 2);
        int rw = wg < Wv - WSv ? 0 : (wg < Wv - SSv ? 1 : 2);
        label_s[tid] = rd * 9 + rh * 3 + rw;
    }
    asm volatile("cp.async.wait_group 0;\n" ::: "memory");
    __syncthreads();

    // ---- S = Q K^T  (this warp: 32 rows x 64 cols, K=32) ----
    float acc[2][8][4];
    #pragma unroll
    for (int a = 0; a < 2; a++)
        #pragma unroll
        for (int bq = 0; bq < 8; bq++)
            #pragma unroll
            for (int t = 0; t < 4; t++) acc[a][bq][t] = 0.f;

    int arow = lane & 15;
    int asel = (lane >> 4) << 3;
    int br   = (lane & 7) + ((lane >> 4) << 3);
    int bkh  = ((lane >> 3) & 1) << 3;
    int m0   = sub * 32;

    #pragma unroll
    for (int ks = 0; ks < 2; ks++) {
        int k0 = ks * 16;
        uint32_t af[2][4];
        #pragma unroll
        for (int mi = 0; mi < 2; mi++)
            ldsm_x4(af[mi][0], af[mi][1], af[mi][2], af[mi][3],
                    sq + (uint32_t)((m0 + mi * 16 + arow) * ATT_STRIDE + k0 + asel) * 2);
        uint32_t bf[8][2];
        #pragma unroll
        for (int nb = 0; nb < 4; nb++)
            ldsm_x4(bf[2*nb][0], bf[2*nb][1], bf[2*nb+1][0], bf[2*nb+1][1],
                    sk + (uint32_t)((nb * 16 + br) * ATT_STRIDE + k0 + bkh) * 2);
        #pragma unroll
        for (int mi = 0; mi < 2; mi++)
            #pragma unroll
            for (int nj = 0; nj < 8; nj++)
                mma_bf16(acc[mi][nj][0], acc[mi][nj][1], acc[mi][nj][2], acc[mi][nj][3],
                         af[mi][0], af[mi][1], af[mi][2], af[mi][3], bf[nj][0], bf[nj][1]);
    }

    // ---- bias + mask + softmax ----
    int r0 = lane >> 2;
    int cq = (lane & 3) * 2;
    int ui[4], li[4];
    #pragma unroll
    for (int mi = 0; mi < 2; mi++)
        #pragma unroll
        for (int hh = 0; hh < 2; hh++) {
            int i = m0 + mi * 16 + hh * 8 + r0;
            ui[mi * 2 + hh] = 49 * (i >> 4) + 7 * ((i >> 2) & 3) + (i & 3);
            li[mi * 2 + hh] = label_s[i];
        }
    int uj[16], lj[16];
    #pragma unroll
    for (int nj = 0; nj < 8; nj++)
        #pragma unroll
        for (int t = 0; t < 2; t++) {
            int j = nj * 8 + cq + t;
            uj[nj * 2 + t] = 49 * (j >> 4) + 7 * ((j >> 2) & 3) + (j & 3);
            lj[nj * 2 + t] = label_s[j];
        }

    const float scale = 0.17677669529663689f;
    #pragma unroll
    for (int mi = 0; mi < 2; mi++)
        #pragma unroll
        for (int nj = 0; nj < 8; nj++)
            #pragma unroll
            for (int hh = 0; hh < 2; hh++)
                #pragma unroll
                for (int t = 0; t < 2; t++) {
                    float s = acc[mi][nj][hh * 2 + t] * scale;
                    int idx = 171 + ui[mi * 2 + hh] - uj[nj * 2 + t];
                    s += rpb_s[idx * 4 + hl];
                    if (li[mi * 2 + hh] != lj[nj * 2 + t]) s -= 100.0f;
                    acc[mi][nj][hh * 2 + t] = s;
                }

    float invs[2][2];
    #pragma unroll
    for (int mi = 0; mi < 2; mi++)
        #pragma unroll
        for (int hh = 0; hh < 2; hh++) {
            float m = -1e30f;
            #pragma unroll
            for (int nj = 0; nj < 8; nj++) {
                m = fmaxf(m, acc[mi][nj][hh * 2]);
                m = fmaxf(m, acc[mi][nj][hh * 2 + 1]);
            }
            m = fmaxf(m, __shfl_xor_sync(0xffffffffu, m, 1));
            m = fmaxf(m, __shfl_xor_sync(0xffffffffu, m, 2));
            float sum = 0.f;
            #pragma unroll
            for (int nj = 0; nj < 8; nj++) {
                float e0 = __expf(acc[mi][nj][hh * 2]     - m);
                float e1 = __expf(acc[mi][nj][hh * 2 + 1] - m);
                acc[mi][nj][hh * 2] = e0; acc[mi][nj][hh * 2 + 1] = e1;
                sum += e0 + e1;
            }
            sum += __shfl_xor_sync(0xffffffffu, sum, 1);
            sum += __shfl_xor_sync(0xffffffffu, sum, 2);
            invs[mi][hh] = 1.0f / sum;
        }

    uint32_t pk[2][8][2];
    #pragma unroll
    for (int mi = 0; mi < 2; mi++)
        #pragma unroll
        for (int t = 0; t < 8; t++) {
            __nv_bfloat162 p0 = __floats2bfloat162_rn(acc[mi][t][0] * invs[mi][0],
                                                      acc[mi][t][1] * invs[mi][0]);
            __nv_bfloat162 p1 = __floats2bfloat162_rn(acc[mi][t][2] * invs[mi][1],
                                                      acc[mi][t][3] * invs[mi][1]);
            pk[mi][t][0] = *(uint32_t*)&p0;
            pk[mi][t][1] = *(uint32_t*)&p1;
        }

    // ---- O = P V  (32 rows x 32 cols, K=64) ----
    float o[2][4][4];
    #pragma unroll
    for (int a = 0; a < 2; a++)
        #pragma unroll
        for (int bq = 0; bq < 4; bq++)
            #pragma unroll
            for (int t = 0; t < 4; t++) o[a][bq][t] = 0.f;

    #pragma unroll
    for (int kt = 0; kt < 4; kt++) {
        uint32_t bv[4][2];
        #pragma unroll
        for (int nb = 0; nb < 2; nb++)
            ldsm_x4t(bv[2*nb][0], bv[2*nb][1], bv[2*nb+1][0], bv[2*nb+1][1],
                     sv + (uint32_t)((kt * 16 + arow) * ATT_STRIDE + nb * 16 + asel) * 2);
        #pragma unroll
        for (int mi = 0; mi < 2; mi++)
            #pragma unroll
            for (int nt = 0; nt < 4; nt++)
                mma_bf16(o[mi][nt][0], o[mi][nt][1], o[mi][nt][2], o[mi][nt][3],
                         pk[mi][2*kt][0], pk[mi][2*kt][1], pk[mi][2*kt+1][0], pk[mi][2*kt+1][1],
                         bv[nt][0], bv[nt][1]);
    }

    #pragma unroll
    for (int mi = 0; mi < 2; mi++)
        #pragma unroll
        for (int nt = 0; nt < 4; nt++)
            #pragma unroll
            for (int hh = 0; hh < 2; hh++) {
                int row = m0 + mi * 16 + hh * 8 + r0;
                int col = head * HDv + nt * 8 + cq;
                __nv_bfloat162 p = __floats2bfloat162_rn(o[mi][nt][hh * 2],
                                                         o[mi][nt][hh * 2 + 1]);
                *(__nv_bfloat162*)(out + ((size_t)wnd * 64 + row) * Cv + col) = p;
            }
}

// ---------------------------------------------------------------------------
// bf16 tensor-core GEMM, 3-stage cp.async pipeline, 1 barrier per K-iter.
// BM=128, BN=128, BK=32, 256 threads (8 warps 4x2), warp tile 32x64.
// EPI: 0 = bf16 out, 1 = fp32 out, 2 = GELU + bf16 out, 3 = +res, fp32 out
#define SA_STRIDE 40
#define SB_STRIDE 136
#define ASTAGE (128 * SA_STRIDE * 2)     // bytes per A stage
#define BSTAGE (32 * SB_STRIDE * 2)      // bytes per B stage
#define GEMM_SMEM (3 * (ASTAGE + BSTAGE))

template<int EPI>
__global__ void __launch_bounds__(256, 2) k_mmagemm(
    const __nv_bfloat16* __restrict__ A, const __nv_bfloat16* __restrict__ Bw,
    const float* __restrict__ bias, void* __restrict__ Cout,
    int M, int N, int K, const float* __restrict__ res) {
    int tid  = threadIdx.x;
    int lane = tid & 31, warp = tid >> 5;
    int wy = warp >> 1, wx = warp & 1;
    int rowBase = blockIdx.y * 128;
    int colBase = blockIdx.x * 128;

    int a_r0 = tid >> 2;
    int a_kc = (tid & 3) * 8;
    int b_k0 = tid >> 4;
    int b_nc = (tid & 15) * 8;

    uint32_t sbase = (uint32_t)__cvta_generic_to_shared(dyn_smem);
    uint32_t sAs[3], sBs[3];
    #pragma unroll
    for (int s = 0; s < 3; s++) {
        sAs[s] = sbase + s * (ASTAGE + BSTAGE);
        sBs[s] = sAs[s] + ASTAGE;
    }

    const int NIT = K >> 5;

    auto issue = [&](int it) {
        int slot = it % 3;
        int k0 = it << 5;
        uint32_t sAu = sAs[slot], sBu = sBs[slot];
        const __nv_bfloat16* Ag = A + (size_t)(rowBase + a_r0) * K + k0 + a_kc;
        cp16(sAu + (uint32_t)(a_r0 * SA_STRIDE + a_kc) * 2, Ag);
        cp16(sAu + (uint32_t)((a_r0 + 64) * SA_STRIDE + a_kc) * 2, Ag + (size_t)64 * K);
        const __nv_bfloat16* Bg = Bw + (size_t)(k0 + b_k0) * N + colBase + b_nc;
        cp16(sBu + (uint32_t)(b_k0 * SB_STRIDE + b_nc) * 2, Bg);
        cp16(sBu + (uint32_t)((b_k0 + 16) * SB_STRIDE + b_nc) * 2, Bg + (size_t)16 * N);
        asm volatile("cp.async.commit_group;\n" ::: "memory");
    };

    issue(0);
    if (NIT > 1) issue(1);

    float acc[2][8][4];
    #pragma unroll
    for (int i = 0; i < 2; i++)
        #pragma unroll
        for (int j = 0; j < 8; j++)
            #pragma unroll
            for (int t = 0; t < 4; t++) acc[i][j][t] = 0.f;

    int m0  = wy * 32;
    int n0w = wx * 64;
    int arow = lane & 15;
    int asel = (lane >> 4) << 3;

    for (int it = 0; it < NIT; it++) {
        if (it + 1 < NIT) asm volatile("cp.async.wait_group 1;\n" ::: "memory");
        else              asm volatile("cp.async.wait_group 0;\n" ::: "memory");
        __syncthreads();
        if (it + 2 < NIT) issue(it + 2);       // overlap next-next stage with compute

        int slot = it % 3;
        uint32_t sAu = sAs[slot], sBu = sBs[slot];

        #pragma unroll
        for (int ks = 0; ks < 2; ks++) {
            int k0 = ks * 16;
            uint32_t a[2][4];
            #pragma unroll
            for (int mi = 0; mi < 2; mi++)
                ldsm_x4(a[mi][0], a[mi][1], a[mi][2], a[mi][3],
                        sAu + (uint32_t)((m0 + mi * 16 + arow) * SA_STRIDE + k0 + asel) * 2);
            uint32_t b[8][2];
            #pragma unroll
            for (int nj = 0; nj < 4; nj++)
                ldsm_x4t(b[2 * nj][0], b[2 * nj][1], b[2 * nj + 1][0], b[2 * nj + 1][1],
                         sBu + (uint32_t)((k0 + (lane & 15)) * SB_STRIDE
                                          + n0w + nj * 16 + ((lane >> 4) << 3)) * 2);
            #pragma unroll
            for (int mi = 0; mi < 2; mi++)
                #pragma unroll
                for (int ni = 0; ni < 8; ni++)
                    mma_bf16(acc[mi][ni][0], acc[mi][ni][1], acc[mi][ni][2], acc[mi][ni][3],
                             a[mi][0], a[mi][1], a[mi][2], a[mi][3], b[ni][0], b[ni][1]);
        }
    }

    int gr = lane >> 2, gc = (lane & 3) * 2;
    #pragma unroll
    for (int mi = 0; mi < 2; mi++) {
        #pragma unroll
        for (int ni = 0; ni < 8; ni++) {
            int col = colBase + n0w + ni * 8 + gc;
            float b0 = bias[col], b1 = bias[col + 1];
            #pragma unroll
            for (int half = 0; half < 2; half++) {
                size_t row = (size_t)(rowBase + m0 + mi * 16 + gr + half * 8);
                float v0 = acc[mi][ni][half * 2 + 0] + b0;
                float v1 = acc[mi][ni][half * 2 + 1] + b1;
                if (EPI == 2) {
                    v0 = 0.5f * v0 * (1.0f + erff(v0 * 0.70710678118654752f));
                    v1 = 0.5f * v1 * (1.0f + erff(v1 * 0.70710678118654752f));
                }
                if (EPI == 3) {
                    v0 += res[row * N + col];
                    v1 += res[row * N + col + 1];
                }
                if (EPI == 0 || EPI == 2) {
                    __nv_bfloat162* p = (__nv_bfloat162*)((__nv_bfloat16*)Cout + row * N + col);
                    *p = __floats2bfloat162_rn(v0, v1);
                } else {
                    float2* p = (float2*)((float*)Cout + row * N + col);
                    *p = make_float2(v0, v1);
                }
            }
        }
    }
}

// ---------------------------------------------------------------------------
extern "C" void kernel_launch(void* const* d_in, const int* in_sizes, int n_in,
                              void* d_out, int out_size) {
    const float* x      = (const float*)d_in[0];
    const float* n1g    = (const float*)d_in[1];
    const float* n1b    = (const float*)d_in[2];
    const float* qkv_w  = (const float*)d_in[3];
    const float* qkv_b  = (const float*)d_in[4];
    const float* proj_w = (const float*)d_in[5];
    const float* proj_b = (const float*)d_in[6];
    const float* rpb    = (const float*)d_in[7];
    const float* n2g    = (const float*)d_in[8];
    const float* n2b    = (const float*)d_in[9];
    const float* fc1_w  = (const float*)d_in[10];
    const float* fc1_b  = (const float*)d_in[11];
    const float* fc2_w  = (const float*)d_in[12];
    const float* fc2_b  = (const float*)d_in[13];
    float* out = (float*)d_out;

    __nv_bfloat16 *ln, *big, *attn, *wts;
    float *proj, *x1;
    cudaGetSymbolAddress((void**)&ln,   g_ln);
    cudaGetSymbolAddress((void**)&big,  g_big);
    cudaGetSymbolAddress((void**)&attn, g_attn);
    cudaGetSymbolAddress((void**)&proj, g_proj);
    cudaGetSymbolAddress((void**)&x1,   g_x1);
    cudaGetSymbolAddress((void**)&wts,  g_w);

    cudaFuncSetAttribute(k_attn_mma, cudaFuncAttributeMaxDynamicSharedMemorySize, ATT_SMEM);
    cudaFuncSetAttribute(k_mmagemm<0>, cudaFuncAttributeMaxDynamicSharedMemorySize, GEMM_SMEM);
    cudaFuncSetAttribute(k_mmagemm<1>, cudaFuncAttributeMaxDynamicSharedMemorySize, GEMM_SMEM);
    cudaFuncSetAttribute(k_mmagemm<2>, cudaFuncAttributeMaxDynamicSharedMemorySize, GEMM_SMEM);
    cudaFuncSetAttribute(k_mmagemm<3>, cudaFuncAttributeMaxDynamicSharedMemorySize, GEMM_SMEM);

    // 0) weights -> bf16
    k_f2bf4<<<(WTOTAL + 255) / 256, 256>>>(qkv_w, proj_w, fc1_w, fc2_w, wts);

    // 1) LN1 + roll + window partition
    k_ln1_v2<<<Tv / 8, 256>>>(x, n1g, n1b, ln);
    // 2) qkv GEMM
    k_mmagemm<0><<<dim3(768 / 128, Tv / 128), 256, GEMM_SMEM>>>(ln, wts + WOFF_QKV, qkv_b, big, Tv, 768, 256, nullptr);
    // 3) attention (4 heads/block)
    k_attn_mma<<<BWIN * 2, 256, ATT_SMEM>>>(big, rpb, attn);
    // 4) proj GEMM
    k_mmagemm<1><<<dim3(256 / 128, Tv / 128), 256, GEMM_SMEM>>>(attn, wts + WOFF_PROJ, proj_b, proj, Tv, 256, 256, nullptr);
    // 5) x1 + LN2
    k_x1_ln2_v2<<<Tv / 8, 256>>>(x, proj, n2g, n2b, x1, ln);
    // 6) fc1 + GELU
    k_mmagemm<2><<<dim3(1024 / 128, Tv / 128), 256, GEMM_SMEM>>>(ln, wts + WOFF_FC1, fc1_b, big, Tv, 1024, 256, nullptr);
    // 7) fc2 + residual
    k_mmagemm<3><<<dim3(256 / 128, Tv / 128), 256, GEMM_SMEM>>>(big, wts + WOFF_FC2, fc2_b, out, Tv, 256, 1024, x1);
}